// round 4
// baseline (speedup 1.0000x reference)
#include <cuda_runtime.h>
#include <cuda_bf16.h>
#include <math.h>

// ---------------------------------------------------------------------------
// Problem constants (fixed by the reference)
// ---------------------------------------------------------------------------
#define MAXN 50000
#define MAXE 800000
#define FIN 128
#define HID 32
#define HEADS 4
#define NCLS 16
#define MLPH 128
#define NEG_SLOPE 0.2f
#define TOPK 8

// ---------------------------------------------------------------------------
// Device scratch (static -> no allocation)
// ---------------------------------------------------------------------------
__device__ int g_is64;
__device__ int d_src[MAXE];
__device__ int d_dst[MAXE];
__device__ int d_csr[MAXE];
__device__ int d_counts[MAXN];
__device__ int d_cursor[MAXN];
__device__ int d_starts[MAXN + 1];
__device__ float d_xl1[MAXN * 128];
__device__ float d_xr1[MAXN * 128];
__device__ float d_score1[MAXE * 4];
__device__ float d_h[MAXN * 128];       // elu(layer1 out)  -> layer2 input
__device__ float d_noise1[MAXN * 128];  // layer1 noise     -> MLP input
__device__ float d_xl2[MAXN * 16];
__device__ float d_xr2[MAXN * 16];
__device__ float d_score2[MAXE];

// ---------------------------------------------------------------------------
// Helpers
// ---------------------------------------------------------------------------
__device__ __forceinline__ float lrelu(float v) { return v > 0.f ? v : NEG_SLOPE * v; }

// 64-bit sort key: (order-preserving float bits << 32) | ~edge_id
// larger score -> larger key; ties: smaller edge id -> larger key
// (matches the reference's stable argsort semantics exactly)
__device__ __forceinline__ unsigned long long makekey(float s, int eid) {
    unsigned u = __float_as_uint(s);
    u = (u & 0x80000000u) ? ~u : (u | 0x80000000u);
    return ((unsigned long long)u << 32) | (unsigned)(~eid);
}
__device__ __forceinline__ float key_score(unsigned long long k) {
    unsigned u = (unsigned)(k >> 32);
    u = (u & 0x80000000u) ? (u ^ 0x80000000u) : ~u;
    return __uint_as_float(u);
}

struct SoftInfo {
    unsigned long long thresh;  // 8th-largest key; 0 => everything kept
    float mk, mn;               // max kept score, max excluded score
    float sk, sn;               // sum exp(s - mk) kept, sum exp(s - mn) excluded
};

// Warp-cooperative top-8 selection + softmax sums for one (dst, head) segment.
__device__ __forceinline__ SoftInfo select_topk8(
    const int* __restrict__ csr, int start, int deg,
    const float* __restrict__ score, int stride, int off, int lane)
{
    const int LK = 8;                    // per-lane key slots -> deg<=256 in regs
    unsigned long long loc[LK];
    bool small = (deg <= 32 * LK);
#pragma unroll
    for (int i = 0; i < LK; ++i) {
        int j = lane + i * 32;
        unsigned long long v = 0ull;
        if (small && j < deg) {
            int eid = csr[start + j];
            v = makekey(score[eid * stride + off], eid);
        }
        loc[i] = v;
    }

    SoftInfo r;
    r.thresh = 0ull; r.mk = 0.f; r.mn = 0.f; r.sk = 0.f; r.sn = 0.f;

    unsigned long long cut = ~0ull;
    int rounds = deg < (TOPK + 1) ? deg : (TOPK + 1);
    for (int t = 0; t < rounds; ++t) {
        unsigned long long best = 0ull;
        if (small) {
#pragma unroll
            for (int i = 0; i < LK; ++i)
                if (loc[i] < cut && loc[i] > best) best = loc[i];
        } else {
            for (int j = lane; j < deg; j += 32) {
                int eid = csr[start + j];
                unsigned long long kk = makekey(score[eid * stride + off], eid);
                if (kk < cut && kk > best) best = kk;
            }
        }
#pragma unroll
        for (int o = 16; o > 0; o >>= 1) {
            unsigned long long x = __shfl_xor_sync(0xffffffffu, best, o);
            if (x > best) best = x;
        }
        if (t == 0)        r.mk = key_score(best);
        if (t == TOPK - 1) r.thresh = best;
        if (t == TOPK)     r.mn = key_score(best);
        cut = best;
    }
    if (deg <= TOPK) r.thresh = 0ull;  // all kept, no noise set

    float sk = 0.f, sn = 0.f;
    if (small) {
#pragma unroll
        for (int i = 0; i < LK; ++i) {
            if (loc[i] != 0ull) {
                float s = key_score(loc[i]);
                if (loc[i] >= r.thresh) sk += expf(s - r.mk);
                else                    sn += expf(s - r.mn);
            }
        }
    } else {
        for (int j = lane; j < deg; j += 32) {
            int eid = csr[start + j];
            float s = score[eid * stride + off];
            unsigned long long kk = makekey(s, eid);
            if (kk >= r.thresh) sk += expf(s - r.mk);
            else                sn += expf(s - r.mn);
        }
    }
#pragma unroll
    for (int o = 16; o > 0; o >>= 1) {
        sk += __shfl_xor_sync(0xffffffffu, sk, o);
        sn += __shfl_xor_sync(0xffffffffu, sn, o);
    }
    r.sk = sk; r.sn = sn;
    return r;
}

// ---------------------------------------------------------------------------
// Preprocessing kernels
// ---------------------------------------------------------------------------
__global__ void zero_kernel(int n) {
    int i = blockIdx.x * blockDim.x + threadIdx.x;
    if (i < n) { d_counts[i] = 0; d_cursor[i] = 0; }
}

// Detect whether edge_index is int64 (odd 32-bit words all zero) or int32.
__global__ void detect_kernel(const void* __restrict__ ei) {
    const unsigned* p = (const unsigned*)ei;
    int t = threadIdx.x;            // 32 threads
    unsigned v = p[2 * t + 1];
    unsigned b = __ballot_sync(0xffffffffu, v != 0u);
    if (t == 0) g_is64 = (b == 0u) ? 1 : 0;
}

__global__ __launch_bounds__(256) void convert_kernel(const void* __restrict__ ei, int E) {
    int e = blockIdx.x * blockDim.x + threadIdx.x;
    if (e >= E) return;
    int s, d;
    if (g_is64) {
        const long long* p = (const long long*)ei;
        s = (int)p[e]; d = (int)p[E + e];
    } else {
        const int* p = (const int*)ei;
        s = p[e]; d = p[E + e];
    }
    d_src[e] = s; d_dst[e] = d;
    atomicAdd(&d_counts[d], 1);
}

__global__ __launch_bounds__(1024) void scan_kernel(int n) {
    __shared__ int wsum[32];
    __shared__ int carry;
    int tid = threadIdx.x, lane = tid & 31, wid = tid >> 5;
    if (tid == 0) carry = 0;
    __syncthreads();
    for (int base = 0; base < n; base += 1024) {
        int i = base + tid;
        int v = (i < n) ? d_counts[i] : 0;
        int x = v;
#pragma unroll
        for (int o = 1; o < 32; o <<= 1) {
            int y = __shfl_up_sync(0xffffffffu, x, o);
            if (lane >= o) x += y;
        }
        if (lane == 31) wsum[wid] = x;
        __syncthreads();
        if (wid == 0) {
            int w = wsum[lane];
#pragma unroll
            for (int o = 1; o < 32; o <<= 1) {
                int y = __shfl_up_sync(0xffffffffu, w, o);
                if (lane >= o) w += y;
            }
            wsum[lane] = w;
        }
        __syncthreads();
        int prefix = carry + (wid ? wsum[wid - 1] : 0);
        if (i < n) d_starts[i] = prefix + x - v;
        int tile_total = wsum[31];
        __syncthreads();
        if (tid == 0) carry += tile_total;
        __syncthreads();
    }
    if (threadIdx.x == 0) d_starts[n] = carry;
}

__global__ __launch_bounds__(256) void scatter_kernel(int E) {
    int e = blockIdx.x * blockDim.x + threadIdx.x;
    if (e >= E) return;
    int d = d_dst[e];
    int pos = d_starts[d] + atomicAdd(&d_cursor[d], 1);
    d_csr[pos] = e;
}

// ---------------------------------------------------------------------------
// GEMM: xl1 = x @ Wl1, xr1 = x @ Wr1   ([N,128]@[128,128] x2)
// ---------------------------------------------------------------------------
__global__ __launch_bounds__(256) void gemm1_kernel(
    const float* __restrict__ x, const float* __restrict__ Wl,
    const float* __restrict__ Wr, int n)
{
    __shared__ float sX[32 * 64];
    __shared__ float sW[64 * 128];
    int tx = threadIdx.x;
    int row0 = blockIdx.x * 32;
    int cg = (tx & 31) * 4;
    int rg = (tx >> 5) * 4;
    float accL[4][4], accR[4][4];
#pragma unroll
    for (int r = 0; r < 4; ++r)
#pragma unroll
        for (int c = 0; c < 4; ++c) { accL[r][c] = 0.f; accR[r][c] = 0.f; }

    for (int kt = 0; kt < 128; kt += 64) {
        for (int i = tx; i < 32 * 64; i += 256) {
            int r = i >> 6, k = i & 63;
            int gr = row0 + r;
            sX[i] = (gr < n) ? x[gr * 128 + kt + k] : 0.f;
        }
        for (int i = tx; i < 64 * 128; i += 256) {
            int k = i >> 7, c = i & 127;
            sW[i] = Wl[(kt + k) * 128 + c];
        }
        __syncthreads();
        for (int k = 0; k < 64; ++k) {
            float xv[4];
#pragma unroll
            for (int r = 0; r < 4; ++r) xv[r] = sX[(rg + r) * 64 + k];
            float4 wv = *(const float4*)&sW[k * 128 + cg];
#pragma unroll
            for (int r = 0; r < 4; ++r) {
                accL[r][0] = fmaf(xv[r], wv.x, accL[r][0]);
                accL[r][1] = fmaf(xv[r], wv.y, accL[r][1]);
                accL[r][2] = fmaf(xv[r], wv.z, accL[r][2]);
                accL[r][3] = fmaf(xv[r], wv.w, accL[r][3]);
            }
        }
        __syncthreads();
        for (int i = tx; i < 64 * 128; i += 256) {
            int k = i >> 7, c = i & 127;
            sW[i] = Wr[(kt + k) * 128 + c];
        }
        __syncthreads();
        for (int k = 0; k < 64; ++k) {
            float xv[4];
#pragma unroll
            for (int r = 0; r < 4; ++r) xv[r] = sX[(rg + r) * 64 + k];
            float4 wv = *(const float4*)&sW[k * 128 + cg];
#pragma unroll
            for (int r = 0; r < 4; ++r) {
                accR[r][0] = fmaf(xv[r], wv.x, accR[r][0]);
                accR[r][1] = fmaf(xv[r], wv.y, accR[r][1]);
                accR[r][2] = fmaf(xv[r], wv.z, accR[r][2]);
                accR[r][3] = fmaf(xv[r], wv.w, accR[r][3]);
            }
        }
        __syncthreads();
    }
#pragma unroll
    for (int r = 0; r < 4; ++r) {
        int gr = row0 + rg + r;
        if (gr < n) {
            *(float4*)&d_xl1[gr * 128 + cg] =
                make_float4(accL[r][0], accL[r][1], accL[r][2], accL[r][3]);
            *(float4*)&d_xr1[gr * 128 + cg] =
                make_float4(accR[r][0], accR[r][1], accR[r][2], accR[r][3]);
        }
    }
}

// ---------------------------------------------------------------------------
// Layer-1 edge scores: one warp per edge, lanes cover 128 channels via float4
// ---------------------------------------------------------------------------
__global__ __launch_bounds__(256) void score1_kernel(const float* __restrict__ att, int E)
{
    int gw = (blockIdx.x * 256 + threadIdx.x) >> 5;
    int lane = threadIdx.x & 31;
    bool valid = gw < E;
    int e = valid ? gw : 0;
    int s = d_src[e], d = d_dst[e];
    float4 a = *(const float4*)&d_xl1[s * 128 + lane * 4];
    float4 b = *(const float4*)&d_xr1[d * 128 + lane * 4];
    float4 w = *(const float4*)&att[lane * 4];
    float p = lrelu(a.x + b.x) * w.x + lrelu(a.y + b.y) * w.y +
              lrelu(a.z + b.z) * w.z + lrelu(a.w + b.w) * w.w;
    p += __shfl_xor_sync(0xffffffffu, p, 1);
    p += __shfl_xor_sync(0xffffffffu, p, 2);
    p += __shfl_xor_sync(0xffffffffu, p, 4);
    if (valid && (lane & 7) == 0) d_score1[e * 4 + (lane >> 3)] = p;
}

// ---------------------------------------------------------------------------
// Layer-1 aggregation: one warp per (node, head); lanes = 32 channels
// ---------------------------------------------------------------------------
__global__ __launch_bounds__(256) void agg1_kernel(const float* __restrict__ b1, int n)
{
    int warp = (blockIdx.x * blockDim.x + threadIdx.x) >> 5;
    int lane = threadIdx.x & 31;
    if (warp >= n * 4) return;
    int node = warp >> 2, h = warp & 3;
    int start = d_starts[node], deg = d_starts[node + 1] - start;

    SoftInfo si = select_topk8(d_csr, start, deg, d_score1, 4, h, lane);
    float invk = 1.f / (si.sk + 1e-16f);
    float invn = 1.f / (si.sn + 1e-16f);

    float acc = 0.f, accn = 0.f;
    int eid = (deg > 0) ? d_csr[start] : 0;
    for (int j = 0; j < deg; ++j) {
        int eid_n = (j + 1 < deg) ? d_csr[start + j + 1] : 0;
        float s = d_score1[eid * 4 + h];
        unsigned long long kk = makekey(s, eid);
        float a, an;
        if (kk >= si.thresh) { a = expf(s - si.mk) * invk; an = 0.f; }
        else                 { an = expf(s - si.mn) * invn; a = 0.f; }
        float v = d_xl1[d_src[eid] * 128 + h * 32 + lane];
        acc  = fmaf(a,  v, acc);
        accn = fmaf(an, v, accn);
        eid = eid_n;
    }
    int col = h * 32 + lane;
    float b = b1[col];
    float o = acc + b;
    d_h[node * 128 + col] = (o > 0.f) ? o : expm1f(o);  // elu fused
    d_noise1[node * 128 + col] = accn + b;
}

// ---------------------------------------------------------------------------
// Layer-2 projections: xl2 = h @ Wl2, xr2 = h @ Wr2   ([N,128]@[128,16] x2)
// ---------------------------------------------------------------------------
__global__ __launch_bounds__(256) void gemm2_kernel(
    const float* __restrict__ Wl2, const float* __restrict__ Wr2, int n)
{
    __shared__ float sW[128 * 32];   // cols 0-15 = Wl2, 16-31 = Wr2
    __shared__ float sX[48 * 128];
    int tx = threadIdx.x;
    int row0 = blockIdx.x * 48;
    for (int i = tx; i < 128 * 16; i += 256) {
        int k = i >> 4, c = i & 15;
        sW[k * 32 + c] = Wl2[i];
        sW[k * 32 + 16 + c] = Wr2[i];
    }
    for (int i = tx; i < 48 * 128; i += 256) {
        int r = i >> 7, k = i & 127;
        int gr = row0 + r;
        sX[i] = (gr < n) ? d_h[gr * 128 + k] : 0.f;
    }
    __syncthreads();
    int col = tx & 31, r0 = (tx >> 5) * 6;
    float acc[6] = {0.f, 0.f, 0.f, 0.f, 0.f, 0.f};
    for (int k = 0; k < 128; ++k) {
        float w = sW[k * 32 + col];
#pragma unroll
        for (int r = 0; r < 6; ++r)
            acc[r] = fmaf(sX[(r0 + r) * 128 + k], w, acc[r]);
    }
#pragma unroll
    for (int r = 0; r < 6; ++r) {
        int gr = row0 + r0 + r;
        if (gr < n) {
            if (col < 16) d_xl2[gr * 16 + col] = acc[r];
            else          d_xr2[gr * 16 + col - 16] = acc[r];
        }
    }
}

// ---------------------------------------------------------------------------
// MLP on noise1: log_softmax(elu(noise1@W1+b1)@W2+b2)  -> out section 1
// ---------------------------------------------------------------------------
__global__ __launch_bounds__(256) void mlp_kernel(
    const float* __restrict__ W1, const float* __restrict__ B1,
    const float* __restrict__ W2, const float* __restrict__ B2,
    float* __restrict__ outp, int n)
{
    __shared__ float buf[10240];  // 40KB, carved per stage
    float* sX = buf;              // 32*64
    float* sW = buf + 2048;       // 64*128
    int tx = threadIdx.x;
    int row0 = blockIdx.x * 32;
    int cg = (tx & 31) * 4;
    int rg = (tx >> 5) * 4;
    float acc[4][4];
#pragma unroll
    for (int r = 0; r < 4; ++r)
#pragma unroll
        for (int c = 0; c < 4; ++c) acc[r][c] = 0.f;

    for (int kt = 0; kt < 128; kt += 64) {
        for (int i = tx; i < 32 * 64; i += 256) {
            int r = i >> 6, k = i & 63;
            int gr = row0 + r;
            sX[i] = (gr < n) ? d_noise1[gr * 128 + kt + k] : 0.f;
        }
        for (int i = tx; i < 64 * 128; i += 256) {
            int k = i >> 7, c = i & 127;
            sW[i] = W1[(kt + k) * 128 + c];
        }
        __syncthreads();
        for (int k = 0; k < 64; ++k) {
            float xv[4];
#pragma unroll
            for (int r = 0; r < 4; ++r) xv[r] = sX[(rg + r) * 64 + k];
            float4 wv = *(const float4*)&sW[k * 128 + cg];
#pragma unroll
            for (int r = 0; r < 4; ++r) {
                acc[r][0] = fmaf(xv[r], wv.x, acc[r][0]);
                acc[r][1] = fmaf(xv[r], wv.y, acc[r][1]);
                acc[r][2] = fmaf(xv[r], wv.z, acc[r][2]);
                acc[r][3] = fmaf(xv[r], wv.w, acc[r][3]);
            }
        }
        __syncthreads();
    }
    // stage 1 epilogue: elu -> tbuf (reuses buf[0..4095])
    float* tbuf = buf;
#pragma unroll
    for (int r = 0; r < 4; ++r)
#pragma unroll
        for (int c = 0; c < 4; ++c) {
            float o = acc[r][c] + B1[cg + c];
            tbuf[(rg + r) * 128 + cg + c] = (o > 0.f) ? o : expm1f(o);
        }
    float* sW2 = buf + 4096;  // 128*16
    for (int i = tx; i < 128 * 16; i += 256) sW2[i] = W2[i];
    __syncthreads();

    float* res = buf + 6144;  // 32*16
    {
        int o = tx * 2;
#pragma unroll
        for (int q = 0; q < 2; ++q) {
            int oo = o + q, r = oo >> 4, c = oo & 15;
            float a = 0.f;
            for (int k = 0; k < 128; ++k)
                a = fmaf(tbuf[r * 128 + k], sW2[k * 16 + c], a);
            res[oo] = a + B2[c];
        }
    }
    __syncthreads();

    // log_softmax over 16 classes; warp wid handles rows 4*wid..4*wid+3
    int lane = tx & 31, wid = tx >> 5;
#pragma unroll
    for (int rr = 0; rr < 4; ++rr) {
        int r = wid * 4 + rr;
        float v = (lane < 16) ? res[r * 16 + lane] : -1e30f;
        float m = v;
#pragma unroll
        for (int o = 8; o > 0; o >>= 1) m = fmaxf(m, __shfl_xor_sync(0xffffffffu, m, o, 16));
        float e = (lane < 16) ? expf(v - m) : 0.f;
        float s = e;
#pragma unroll
        for (int o = 8; o > 0; o >>= 1) s += __shfl_xor_sync(0xffffffffu, s, o, 16);
        int gr = row0 + r;
        if (lane < 16 && gr < n) outp[gr * 16 + lane] = v - m - logf(s);
    }
}

// ---------------------------------------------------------------------------
// Layer-2 edge scores: 4 lanes per edge over 16 channels
// ---------------------------------------------------------------------------
__global__ __launch_bounds__(256) void score2_kernel(const float* __restrict__ att2, int E)
{
    int t = blockIdx.x * 256 + threadIdx.x;
    int e = t >> 2, q = t & 3;
    bool valid = e < E;
    int ee = valid ? e : 0;
    int s = d_src[ee], d = d_dst[ee];
    float4 a = *(const float4*)&d_xl2[s * 16 + q * 4];
    float4 b = *(const float4*)&d_xr2[d * 16 + q * 4];
    float4 w = *(const float4*)&att2[q * 4];
    float p = lrelu(a.x + b.x) * w.x + lrelu(a.y + b.y) * w.y +
              lrelu(a.z + b.z) * w.z + lrelu(a.w + b.w) * w.w;
    p += __shfl_xor_sync(0xffffffffu, p, 1);
    p += __shfl_xor_sync(0xffffffffu, p, 2);
    if (valid && q == 0) d_score2[e] = p;
}

// ---------------------------------------------------------------------------
// Layer-2 aggregation + fused log_softmax of both outputs
// ---------------------------------------------------------------------------
__global__ __launch_bounds__(256) void agg2_kernel(
    const float* __restrict__ b2, float* __restrict__ out0,
    float* __restrict__ out2, int n)
{
    int node = (blockIdx.x * blockDim.x + threadIdx.x) >> 5;
    int lane = threadIdx.x & 31;
    if (node >= n) return;
    int start = d_starts[node], deg = d_starts[node + 1] - start;

    SoftInfo si = select_topk8(d_csr, start, deg, d_score2, 1, 0, lane);
    float invk = 1.f / (si.sk + 1e-16f);
    float invn = 1.f / (si.sn + 1e-16f);

    float acc = 0.f, accn = 0.f;
    int eid = (deg > 0) ? d_csr[start] : 0;
    for (int j = 0; j < deg; ++j) {
        int eid_n = (j + 1 < deg) ? d_csr[start + j + 1] : 0;
        float s = d_score2[eid];
        unsigned long long kk = makekey(s, eid);
        float a, an;
        if (kk >= si.thresh) { a = expf(s - si.mk) * invk; an = 0.f; }
        else                 { an = expf(s - si.mn) * invn; a = 0.f; }
        float v = (lane < 16) ? d_xl2[d_src[eid] * 16 + lane] : 0.f;
        acc  = fmaf(a,  v, acc);
        accn = fmaf(an, v, accn);
        eid = eid_n;
    }
    float b = (lane < 16) ? b2[lane] : 0.f;
    float o = acc + b;
    float no = accn + b;

    // log_softmax over 16 (lanes 16-31 form their own shfl group; harmless)
    float m = o;
#pragma unroll
    for (int q = 8; q > 0; q >>= 1) m = fmaxf(m, __shfl_xor_sync(0xffffffffu, m, q, 16));
    float e1 = expf(o - m);
    float s1 = e1;
#pragma unroll
    for (int q = 8; q > 0; q >>= 1) s1 += __shfl_xor_sync(0xffffffffu, s1, q, 16);

    float m2 = no;
#pragma unroll
    for (int q = 8; q > 0; q >>= 1) m2 = fmaxf(m2, __shfl_xor_sync(0xffffffffu, m2, q, 16));
    float e2 = expf(no - m2);
    float s2 = e2;
#pragma unroll
    for (int q = 8; q > 0; q >>= 1) s2 += __shfl_xor_sync(0xffffffffu, s2, q, 16);

    if (lane < 16) {
        out0[node * 16 + lane] = o - m - logf(s1);
        out2[node * 16 + lane] = no - m2 - logf(s2);
    }
}

// ---------------------------------------------------------------------------
// Launch
// ---------------------------------------------------------------------------
extern "C" void kernel_launch(void* const* d_in, const int* in_sizes, int n_in,
                              void* d_out, int out_size)
{
    const float* x    = (const float*)d_in[0];
    const void*  ei   = d_in[1];
    // d_in[2] = attn_topk (always 8)
    const float* Wl1  = (const float*)d_in[3];
    const float* Wr1  = (const float*)d_in[4];
    const float* att1 = (const float*)d_in[5];
    const float* b1   = (const float*)d_in[6];
    const float* Wl2  = (const float*)d_in[7];
    const float* Wr2  = (const float*)d_in[8];
    const float* att2 = (const float*)d_in[9];
    const float* b2   = (const float*)d_in[10];
    const float* l1w  = (const float*)d_in[11];
    const float* l1b  = (const float*)d_in[12];
    const float* l2w  = (const float*)d_in[13];
    const float* l2b  = (const float*)d_in[14];

    int N = in_sizes[0] / 128;
    int E = in_sizes[1] / 2;
    if (N > MAXN) N = MAXN;
    if (E > MAXE) E = MAXE;

    float* out = (float*)d_out;
    float* out_s0 = out;                 // log_softmax(layer2 out)
    float* out_s1 = out + (size_t)N * 16; // log_softmax(MLP(noise1))
    float* out_s2 = out + (size_t)2 * N * 16; // log_softmax(noise2)

    // Preprocess: dtype detect, convert, degree count, CSR build
    zero_kernel<<<(N + 255) / 256, 256>>>(N);
    detect_kernel<<<1, 32>>>(ei);
    convert_kernel<<<(E + 255) / 256, 256>>>(ei, E);
    scan_kernel<<<1, 1024>>>(N);
    scatter_kernel<<<(E + 255) / 256, 256>>>(E);

    // Layer 1
    gemm1_kernel<<<(N + 31) / 32, 256>>>(x, Wl1, Wr1, N);
    score1_kernel<<<(E + 7) / 8, 256>>>(att1, E);
    agg1_kernel<<<(N * 4 + 7) / 8, 256>>>(b1, N);

    // Layer 2 projections + MLP branch
    gemm2_kernel<<<(N + 47) / 48, 256>>>(Wl2, Wr2, N);
    mlp_kernel<<<(N + 31) / 32, 256>>>(l1w, l1b, l2w, l2b, out_s1, N);

    // Layer 2 attention
    score2_kernel<<<(E + 63) / 64, 256>>>(att2, E);
    agg2_kernel<<<(N + 7) / 8, 256>>>(b2, out_s0, out_s2, N);
}

// round 6
// speedup vs baseline: 1.3189x; 1.3189x over previous
#include <cuda_runtime.h>
#include <cuda_bf16.h>
#include <math.h>

// ---------------------------------------------------------------------------
// Problem constants (fixed by the reference)
// ---------------------------------------------------------------------------
#define MAXN 50000
#define MAXE 800000
#define NEG_SLOPE 0.2f
#define TOPK 8

// ---------------------------------------------------------------------------
// Device scratch (static -> no allocation)
// ---------------------------------------------------------------------------
__device__ int g_is64;
__device__ int d_src[MAXE];
__device__ int d_dst[MAXE];
__device__ int d_csr[MAXE];       // CSR pos -> edge id
__device__ int d_csr_src[MAXE];   // CSR pos -> src node
__device__ int d_csr_dst[MAXE];   // CSR pos -> dst node
__device__ int d_counts[MAXN];
__device__ int d_cursor[MAXN];
__device__ int d_starts[MAXN + 1];
__device__ float d_xl1[MAXN * 128];
__device__ float d_xr1[MAXN * 128];
__device__ float d_score1[MAXE * 4];   // planar by head, CSR order: [h*E + pos]
__device__ float d_h[MAXN * 128];      // elu(layer1 out)  -> layer2 input
__device__ float d_noise1[MAXN * 128]; // layer1 noise     -> MLP input
__device__ float d_xl2[MAXN * 16];
__device__ float d_xr2[MAXN * 16];
__device__ float d_score2[MAXE];       // CSR order

// ---------------------------------------------------------------------------
// Helpers
// ---------------------------------------------------------------------------
__device__ __forceinline__ float lrelu(float v) { return v > 0.f ? v : NEG_SLOPE * v; }

// 64-bit sort key: (order-preserving float bits << 32) | ~edge_id
// larger score -> larger key; ties: smaller edge id -> larger key
__device__ __forceinline__ unsigned long long makekey(float s, int eid) {
    unsigned u = __float_as_uint(s);
    u = (u & 0x80000000u) ? ~u : (u | 0x80000000u);
    return ((unsigned long long)u << 32) | (unsigned)(~eid);
}

// ---------------------------------------------------------------------------
// Preprocessing
// ---------------------------------------------------------------------------
__global__ void detect_kernel(const void* __restrict__ ei) {
    const unsigned* p = (const unsigned*)ei;
    int t = threadIdx.x;  // 32 threads
    unsigned v = p[2 * t + 1];
    unsigned b = __ballot_sync(0xffffffffu, v != 0u);
    if (t == 0) g_is64 = (b == 0u) ? 1 : 0;
}

__global__ __launch_bounds__(256) void convert_kernel(const void* __restrict__ ei, int E) {
    int e = blockIdx.x * blockDim.x + threadIdx.x;
    if (e >= E) return;
    int s, d;
    if (g_is64) {
        const long long* p = (const long long*)ei;
        s = (int)p[e]; d = (int)p[E + e];
    } else {
        const int* p = (const int*)ei;
        s = p[e]; d = p[E + e];
    }
    d_src[e] = s; d_dst[e] = d;
    atomicAdd(&d_counts[d], 1);
}

// Thread-coarse single-block scan: each thread owns a contiguous chunk.
__global__ __launch_bounds__(1024) void scan_kernel(int n) {
    __shared__ int wsum[32];
    int tid = threadIdx.x, lane = tid & 31, wid = tid >> 5;
    int ch = (n + 1023) >> 10;
    int base = tid * ch;
    int sum = 0;
    for (int i = 0; i < ch; ++i) {
        int idx = base + i;
        if (idx < n) sum += d_counts[idx];
    }
    int x = sum;
#pragma unroll
    for (int o = 1; o < 32; o <<= 1) {
        int y = __shfl_up_sync(0xffffffffu, x, o);
        if (lane >= o) x += y;
    }
    if (lane == 31) wsum[wid] = x;
    __syncthreads();
    if (wid == 0) {
        int w = wsum[lane];
#pragma unroll
        for (int o = 1; o < 32; o <<= 1) {
            int y = __shfl_up_sync(0xffffffffu, w, o);
            if (lane >= o) w += y;
        }
        wsum[lane] = w;
    }
    __syncthreads();
    int pre = (wid ? wsum[wid - 1] : 0) + x - sum;  // exclusive prefix
    for (int i = 0; i < ch; ++i) {
        int idx = base + i;
        if (idx < n) { d_starts[idx] = pre; pre += d_counts[idx]; }
    }
    if (tid == 1023) d_starts[n] = pre;
}

__global__ __launch_bounds__(256) void scatter_kernel(int E) {
    int e = blockIdx.x * blockDim.x + threadIdx.x;
    if (e >= E) return;
    int d = d_dst[e];
    int pos = d_starts[d] + atomicAdd(&d_cursor[d], 1);
    d_csr[pos] = e;
    d_csr_src[pos] = d_src[e];
    d_csr_dst[pos] = d;
}

// ---------------------------------------------------------------------------
// GEMM: xl1 = x @ Wl1, xr1 = x @ Wr1   ([N,128]@[128,128] x2)
// ---------------------------------------------------------------------------
__global__ __launch_bounds__(256) void gemm1_kernel(
    const float* __restrict__ x, const float* __restrict__ Wl,
    const float* __restrict__ Wr, int n)
{
    __shared__ float sX[32 * 64];
    __shared__ float sW[64 * 128];
    int tx = threadIdx.x;
    int row0 = blockIdx.x * 32;
    int cg = (tx & 31) * 4;
    int rg = (tx >> 5) * 4;
    float accL[4][4], accR[4][4];
#pragma unroll
    for (int r = 0; r < 4; ++r)
#pragma unroll
        for (int c = 0; c < 4; ++c) { accL[r][c] = 0.f; accR[r][c] = 0.f; }

    for (int kt = 0; kt < 128; kt += 64) {
        for (int i = tx; i < 32 * 64; i += 256) {
            int r = i >> 6, k = i & 63;
            int gr = row0 + r;
            sX[i] = (gr < n) ? x[gr * 128 + kt + k] : 0.f;
        }
        for (int i = tx; i < 64 * 128; i += 256) {
            int k = i >> 7, c = i & 127;
            sW[i] = Wl[(kt + k) * 128 + c];
        }
        __syncthreads();
        for (int k = 0; k < 64; ++k) {
            float xv[4];
#pragma unroll
            for (int r = 0; r < 4; ++r) xv[r] = sX[(rg + r) * 64 + k];
            float4 wv = *(const float4*)&sW[k * 128 + cg];
#pragma unroll
            for (int r = 0; r < 4; ++r) {
                accL[r][0] = fmaf(xv[r], wv.x, accL[r][0]);
                accL[r][1] = fmaf(xv[r], wv.y, accL[r][1]);
                accL[r][2] = fmaf(xv[r], wv.z, accL[r][2]);
                accL[r][3] = fmaf(xv[r], wv.w, accL[r][3]);
            }
        }
        __syncthreads();
        for (int i = tx; i < 64 * 128; i += 256) {
            int k = i >> 7, c = i & 127;
            sW[i] = Wr[(kt + k) * 128 + c];
        }
        __syncthreads();
        for (int k = 0; k < 64; ++k) {
            float xv[4];
#pragma unroll
            for (int r = 0; r < 4; ++r) xv[r] = sX[(rg + r) * 64 + k];
            float4 wv = *(const float4*)&sW[k * 128 + cg];
#pragma unroll
            for (int r = 0; r < 4; ++r) {
                accR[r][0] = fmaf(xv[r], wv.x, accR[r][0]);
                accR[r][1] = fmaf(xv[r], wv.y, accR[r][1]);
                accR[r][2] = fmaf(xv[r], wv.z, accR[r][2]);
                accR[r][3] = fmaf(xv[r], wv.w, accR[r][3]);
            }
        }
        __syncthreads();
    }
#pragma unroll
    for (int r = 0; r < 4; ++r) {
        int gr = row0 + rg + r;
        if (gr < n) {
            *(float4*)&d_xl1[gr * 128 + cg] =
                make_float4(accL[r][0], accL[r][1], accL[r][2], accL[r][3]);
            *(float4*)&d_xr1[gr * 128 + cg] =
                make_float4(accR[r][0], accR[r][1], accR[r][2], accR[r][3]);
        }
    }
}

// ---------------------------------------------------------------------------
// Layer-1 edge scores in CSR order: one warp per CSR position.
// Writes planar per-head scores: d_score1[h*E + pos]
// ---------------------------------------------------------------------------
__global__ __launch_bounds__(256) void score1_kernel(const float* __restrict__ att, int E)
{
    int pos = (blockIdx.x * 256 + threadIdx.x) >> 5;
    int lane = threadIdx.x & 31;
    bool valid = pos < E;
    int p = valid ? pos : 0;
    int s = d_csr_src[p], d = d_csr_dst[p];
    float4 a = *(const float4*)&d_xl1[s * 128 + lane * 4];
    float4 b = *(const float4*)&d_xr1[d * 128 + lane * 4];
    float4 w = *(const float4*)&att[lane * 4];
    float pr = lrelu(a.x + b.x) * w.x + lrelu(a.y + b.y) * w.y +
               lrelu(a.z + b.z) * w.z + lrelu(a.w + b.w) * w.w;
    pr += __shfl_xor_sync(0xffffffffu, pr, 1);
    pr += __shfl_xor_sync(0xffffffffu, pr, 2);
    pr += __shfl_xor_sync(0xffffffffu, pr, 4);
    if (valid && (lane & 7) == 0) d_score1[(size_t)(lane >> 3) * E + p] = pr;
}

// ---------------------------------------------------------------------------
// Layer-1 aggregation: one warp per (node, head); lanes = 32 channels.
// Register-resident selection + weight broadcast; unrolled gather loop.
// ---------------------------------------------------------------------------
__global__ __launch_bounds__(256) void agg1_kernel(const float* __restrict__ b1, int n, int E)
{
    const unsigned F = 0xffffffffu;
    int warp = (blockIdx.x * blockDim.x + threadIdx.x) >> 5;
    int lane = threadIdx.x & 31;
    if (warp >= n * 4) return;
    int node = warp >> 2, h = warp & 3;
    int start = d_starts[node], deg = d_starts[node + 1] - start;
    const float* __restrict__ sc_plane = d_score1 + (size_t)h * E;

    const int LK = 4;
    bool small = (deg <= 32 * LK);
    unsigned long long key[LK];
    float sc[LK];
    int srcv[LK];
#pragma unroll
    for (int i = 0; i < LK; ++i) {
        int j = lane + 32 * i;
        key[i] = 0ull; sc[i] = 0.f; srcv[i] = 0;
        if (small && j < deg) {
            int p = start + j;
            float s = sc_plane[p];
            key[i] = makekey(s, d_csr[p]);
            sc[i] = s;
            srcv[i] = d_csr_src[p];
        }
    }

    // selection: find top-1 (mk), 8th (thresh), 9th (mn)
    unsigned long long thresh = 0ull, cut = ~0ull;
    float mk = 0.f, mn = 0.f;
    int rounds = deg < (TOPK + 1) ? deg : (TOPK + 1);
    for (int t = 0; t < rounds; ++t) {
        unsigned long long best = 0ull;
        if (small) {
#pragma unroll
            for (int i = 0; i < LK; ++i)
                if (key[i] < cut && key[i] > best) best = key[i];
        } else {
            for (int j = lane; j < deg; j += 32) {
                int p = start + j;
                unsigned long long kk = makekey(sc_plane[p], d_csr[p]);
                if (kk < cut && kk > best) best = kk;
            }
        }
#pragma unroll
        for (int o = 16; o > 0; o >>= 1) {
            unsigned long long y = __shfl_xor_sync(F, best, o);
            if (y > best) best = y;
        }
        {
            unsigned u = (unsigned)(best >> 32);
            u = (u & 0x80000000u) ? (u ^ 0x80000000u) : ~u;
            float s = __uint_as_float(u);
            if (t == 0) mk = s;
            if (t == TOPK) mn = s;
        }
        if (t == TOPK - 1) thresh = best;
        cut = best;
    }
    if (deg <= TOPK) thresh = 0ull;

    // softmax sums
    float sk = 0.f, sn = 0.f;
    if (small) {
#pragma unroll
        for (int i = 0; i < LK; ++i) {
            if (key[i] != 0ull) {
                if (key[i] >= thresh) sk += expf(sc[i] - mk);
                else                  sn += expf(sc[i] - mn);
            }
        }
    } else {
        for (int j = lane; j < deg; j += 32) {
            int p = start + j;
            float s = sc_plane[p];
            unsigned long long kk = makekey(s, d_csr[p]);
            if (kk >= thresh) sk += expf(s - mk);
            else              sn += expf(s - mn);
        }
    }
#pragma unroll
    for (int o = 16; o > 0; o >>= 1) {
        sk += __shfl_xor_sync(F, sk, o);
        sn += __shfl_xor_sync(F, sn, o);
    }
    float invk = 1.f / (sk + 1e-16f);
    float invn = 1.f / (sn + 1e-16f);

    float acc = 0.f, accn = 0.f;
    if (small) {
        // packed weight: kept -> +alpha, noise -> -alpha_n, empty -> 0
        float w[LK];
#pragma unroll
        for (int i = 0; i < LK; ++i) {
            w[i] = 0.f;
            if (key[i] != 0ull) {
                if (key[i] >= thresh) w[i] = expf(sc[i] - mk) * invk;
                else                  w[i] = -(expf(sc[i] - mn) * invn);
            }
        }
#pragma unroll
        for (int slot = 0; slot < LK; ++slot) {
            int base = slot * 32;
            if (base < deg) {
                int cnt = deg - base; if (cnt > 32) cnt = 32;
                int cnt4 = (cnt + 3) & ~3;
                for (int o = 0; o < cnt4; o += 4) {
#pragma unroll
                    for (int u = 0; u < 4; ++u) {
                        float ww = __shfl_sync(F, w[slot], o + u);
                        int si = __shfl_sync(F, srcv[slot], o + u);
                        float v = d_xl1[si * 128 + h * 32 + lane];
                        acc  = fmaf(fmaxf(ww, 0.f), v, acc);
                        accn = fmaf(fmaxf(-ww, 0.f), v, accn);
                    }
                }
            }
        }
    } else {
        for (int j = 0; j < deg; ++j) {
            int p = start + j;
            float s = sc_plane[p];
            unsigned long long kk = makekey(s, d_csr[p]);
            float a = 0.f, an = 0.f;
            if (kk >= thresh) a = expf(s - mk) * invk;
            else              an = expf(s - mn) * invn;
            float v = d_xl1[d_csr_src[p] * 128 + h * 32 + lane];
            acc  = fmaf(a, v, acc);
            accn = fmaf(an, v, accn);
        }
    }

    int col = h * 32 + lane;
    float b = b1[col];
    float o = acc + b;
    d_h[node * 128 + col] = (o > 0.f) ? o : expm1f(o);  // elu fused
    d_noise1[node * 128 + col] = accn + b;
}

// ---------------------------------------------------------------------------
// Layer-2 projections: xl2 = h @ Wl2, xr2 = h @ Wr2   ([N,128]@[128,16] x2)
// ---------------------------------------------------------------------------
__global__ __launch_bounds__(256) void gemm2_kernel(
    const float* __restrict__ Wl2, const float* __restrict__ Wr2, int n)
{
    __shared__ float sW[128 * 32];   // cols 0-15 = Wl2, 16-31 = Wr2
    __shared__ float sX[48 * 128];
    int tx = threadIdx.x;
    int row0 = blockIdx.x * 48;
    for (int i = tx; i < 128 * 16; i += 256) {
        int k = i >> 4, c = i & 15;
        sW[k * 32 + c] = Wl2[i];
        sW[k * 32 + 16 + c] = Wr2[i];
    }
    for (int i = tx; i < 48 * 128; i += 256) {
        int r = i >> 7, k = i & 127;
        int gr = row0 + r;
        sX[i] = (gr < n) ? d_h[gr * 128 + k] : 0.f;
    }
    __syncthreads();
    int col = tx & 31, r0 = (tx >> 5) * 6;
    float acc[6] = {0.f, 0.f, 0.f, 0.f, 0.f, 0.f};
    for (int k = 0; k < 128; ++k) {
        float w = sW[k * 32 + col];
#pragma unroll
        for (int r = 0; r < 6; ++r)
            acc[r] = fmaf(sX[(r0 + r) * 128 + k], w, acc[r]);
    }
#pragma unroll
    for (int r = 0; r < 6; ++r) {
        int gr = row0 + r0 + r;
        if (gr < n) {
            if (col < 16) d_xl2[gr * 16 + col] = acc[r];
            else          d_xr2[gr * 16 + col - 16] = acc[r];
        }
    }
}

// ---------------------------------------------------------------------------
// MLP on noise1: log_softmax(elu(noise1@W1+b1)@W2+b2)  -> out section 1
// ---------------------------------------------------------------------------
__global__ __launch_bounds__(256) void mlp_kernel(
    const float* __restrict__ W1, const float* __restrict__ B1,
    const float* __restrict__ W2, const float* __restrict__ B2,
    float* __restrict__ outp, int n)
{
    __shared__ float buf[10240];  // 40KB, carved per stage
    float* sX = buf;              // 32*64
    float* sW = buf + 2048;       // 64*128
    int tx = threadIdx.x;
    int row0 = blockIdx.x * 32;
    int cg = (tx & 31) * 4;
    int rg = (tx >> 5) * 4;
    float acc[4][4];
#pragma unroll
    for (int r = 0; r < 4; ++r)
#pragma unroll
        for (int c = 0; c < 4; ++c) acc[r][c] = 0.f;

    for (int kt = 0; kt < 128; kt += 64) {
        for (int i = tx; i < 32 * 64; i += 256) {
            int r = i >> 6, k = i & 63;
            int gr = row0 + r;
            sX[i] = (gr < n) ? d_noise1[gr * 128 + kt + k] : 0.f;
        }
        for (int i = tx; i < 64 * 128; i += 256) {
            int k = i >> 7, c = i & 127;
            sW[i] = W1[(kt + k) * 128 + c];
        }
        __syncthreads();
        for (int k = 0; k < 64; ++k) {
            float xv[4];
#pragma unroll
            for (int r = 0; r < 4; ++r) xv[r] = sX[(rg + r) * 64 + k];
            float4 wv = *(const float4*)&sW[k * 128 + cg];
#pragma unroll
            for (int r = 0; r < 4; ++r) {
                acc[r][0] = fmaf(xv[r], wv.x, acc[r][0]);
                acc[r][1] = fmaf(xv[r], wv.y, acc[r][1]);
                acc[r][2] = fmaf(xv[r], wv.z, acc[r][2]);
                acc[r][3] = fmaf(xv[r], wv.w, acc[r][3]);
            }
        }
        __syncthreads();
    }
    float* tbuf = buf;
#pragma unroll
    for (int r = 0; r < 4; ++r)
#pragma unroll
        for (int c = 0; c < 4; ++c) {
            float o = acc[r][c] + B1[cg + c];
            tbuf[(rg + r) * 128 + cg + c] = (o > 0.f) ? o : expm1f(o);
        }
    float* sW2 = buf + 4096;  // 128*16
    for (int i = tx; i < 128 * 16; i += 256) sW2[i] = W2[i];
    __syncthreads();

    float* res = buf + 6144;  // 32*16
    {
        int o = tx * 2;
#pragma unroll
        for (int q = 0; q < 2; ++q) {
            int oo = o + q, r = oo >> 4, c = oo & 15;
            float a = 0.f;
            for (int k = 0; k < 128; ++k)
                a = fmaf(tbuf[r * 128 + k], sW2[k * 16 + c], a);
            res[oo] = a + B2[c];
        }
    }
    __syncthreads();

    int lane = tx & 31, wid = tx >> 5;
#pragma unroll
    for (int rr = 0; rr < 4; ++rr) {
        int r = wid * 4 + rr;
        float v = (lane < 16) ? res[r * 16 + lane] : -1e30f;
        float m = v;
#pragma unroll
        for (int o = 8; o > 0; o >>= 1) m = fmaxf(m, __shfl_xor_sync(0xffffffffu, m, o, 16));
        float e = (lane < 16) ? expf(v - m) : 0.f;
        float s = e;
#pragma unroll
        for (int o = 8; o > 0; o >>= 1) s += __shfl_xor_sync(0xffffffffu, s, o, 16);
        int gr = row0 + r;
        if (lane < 16 && gr < n) outp[gr * 16 + lane] = v - m - logf(s);
    }
}

// ---------------------------------------------------------------------------
// Layer-2 edge scores in CSR order: 4 lanes per position
// ---------------------------------------------------------------------------
__global__ __launch_bounds__(256) void score2_kernel(const float* __restrict__ att2, int E)
{
    int t = blockIdx.x * 256 + threadIdx.x;
    int pos = t >> 2, q = t & 3;
    bool valid = pos < E;
    int p = valid ? pos : 0;
    int s = d_csr_src[p], d = d_csr_dst[p];
    float4 a = *(const float4*)&d_xl2[s * 16 + q * 4];
    float4 b = *(const float4*)&d_xr2[d * 16 + q * 4];
    float4 w = *(const float4*)&att2[q * 4];
    float pr = lrelu(a.x + b.x) * w.x + lrelu(a.y + b.y) * w.y +
               lrelu(a.z + b.z) * w.z + lrelu(a.w + b.w) * w.w;
    pr += __shfl_xor_sync(0xffffffffu, pr, 1);
    pr += __shfl_xor_sync(0xffffffffu, pr, 2);
    if (valid && q == 0) d_score2[p] = pr;
}

// ---------------------------------------------------------------------------
// Layer-2 aggregation + fused log_softmax of both outputs
// ---------------------------------------------------------------------------
__global__ __launch_bounds__(256) void agg2_kernel(
    const float* __restrict__ b2, float* __restrict__ out0,
    float* __restrict__ out2, int n)
{
    const unsigned F = 0xffffffffu;
    int node = (blockIdx.x * blockDim.x + threadIdx.x) >> 5;
    int lane = threadIdx.x & 31;
    if (node >= n) return;
    int start = d_starts[node], deg = d_starts[node + 1] - start;

    const int LK = 4;
    bool small = (deg <= 32 * LK);
    unsigned long long key[LK];
    float sc[LK];
    int srcv[LK];
#pragma unroll
    for (int i = 0; i < LK; ++i) {
        int j = lane + 32 * i;
        key[i] = 0ull; sc[i] = 0.f; srcv[i] = 0;
        if (small && j < deg) {
            int p = start + j;
            float s = d_score2[p];
            key[i] = makekey(s, d_csr[p]);
            sc[i] = s;
            srcv[i] = d_csr_src[p];
        }
    }

    unsigned long long thresh = 0ull, cut = ~0ull;
    float mk = 0.f, mn = 0.f;
    int rounds = deg < (TOPK + 1) ? deg : (TOPK + 1);
    for (int t = 0; t < rounds; ++t) {
        unsigned long long best = 0ull;
        if (small) {
#pragma unroll
            for (int i = 0; i < LK; ++i)
                if (key[i] < cut && key[i] > best) best = key[i];
        } else {
            for (int j = lane; j < deg; j += 32) {
                int p = start + j;
                unsigned long long kk = makekey(d_score2[p], d_csr[p]);
                if (kk < cut && kk > best) best = kk;
            }
        }
#pragma unroll
        for (int o = 16; o > 0; o >>= 1) {
            unsigned long long y = __shfl_xor_sync(F, best, o);
            if (y > best) best = y;
        }
        {
            unsigned u = (unsigned)(best >> 32);
            u = (u & 0x80000000u) ? (u ^ 0x80000000u) : ~u;
            float s = __uint_as_float(u);
            if (t == 0) mk = s;
            if (t == TOPK) mn = s;
        }
        if (t == TOPK - 1) thresh = best;
        cut = best;
    }
    if (deg <= TOPK) thresh = 0ull;

    float sk = 0.f, sn = 0.f;
    if (small) {
#pragma unroll
        for (int i = 0; i < LK; ++i) {
            if (key[i] != 0ull) {
                if (key[i] >= thresh) sk += expf(sc[i] - mk);
                else                  sn += expf(sc[i] - mn);
            }
        }
    } else {
        for (int j = lane; j < deg; j += 32) {
            int p = start + j;
            float s = d_score2[p];
            unsigned long long kk = makekey(s, d_csr[p]);
            if (kk >= thresh) sk += expf(s - mk);
            else              sn += expf(s - mn);
        }
    }
#pragma unroll
    for (int o = 16; o > 0; o >>= 1) {
        sk += __shfl_xor_sync(F, sk, o);
        sn += __shfl_xor_sync(F, sn, o);
    }
    float invk = 1.f / (sk + 1e-16f);
    float invn = 1.f / (sn + 1e-16f);

    float acc = 0.f, accn = 0.f;
    if (small) {
        float w[LK];
#pragma unroll
        for (int i = 0; i < LK; ++i) {
            w[i] = 0.f;
            if (key[i] != 0ull) {
                if (key[i] >= thresh) w[i] = expf(sc[i] - mk) * invk;
                else                  w[i] = -(expf(sc[i] - mn) * invn);
            }
        }
#pragma unroll
        for (int slot = 0; slot < LK; ++slot) {
            int base = slot * 32;
            if (base < deg) {
                int cnt = deg - base; if (cnt > 32) cnt = 32;
                int cnt4 = (cnt + 3) & ~3;
                for (int o = 0; o < cnt4; o += 4) {
#pragma unroll
                    for (int u = 0; u < 4; ++u) {
                        float ww = __shfl_sync(F, w[slot], o + u);
                        int si = __shfl_sync(F, srcv[slot], o + u);
                        float v = (lane < 16) ? d_xl2[si * 16 + lane] : 0.f;
                        acc  = fmaf(fmaxf(ww, 0.f), v, acc);
                        accn = fmaf(fmaxf(-ww, 0.f), v, accn);
                    }
                }
            }
        }
    } else {
        for (int j = 0; j < deg; ++j) {
            int p = start + j;
            float s = d_score2[p];
            unsigned long long kk = makekey(s, d_csr[p]);
            float a = 0.f, an = 0.f;
            if (kk >= thresh) a = expf(s - mk) * invk;
            else              an = expf(s - mn) * invn;
            float v = (lane < 16) ? d_xl2[d_csr_src[p] * 16 + lane] : 0.f;
            acc  = fmaf(a, v, acc);
            accn = fmaf(an, v, accn);
        }
    }

    float b = (lane < 16) ? b2[lane] : 0.f;
    float o = acc + b;
    float no = accn + b;

    float m = o;
#pragma unroll
    for (int q = 8; q > 0; q >>= 1) m = fmaxf(m, __shfl_xor_sync(F, m, q, 16));
    float e1 = expf(o - m);
    float s1 = e1;
#pragma unroll
    for (int q = 8; q > 0; q >>= 1) s1 += __shfl_xor_sync(F, s1, q, 16);

    float m2 = no;
#pragma unroll
    for (int q = 8; q > 0; q >>= 1) m2 = fmaxf(m2, __shfl_xor_sync(F, m2, q, 16));
    float e2 = expf(no - m2);
    float s2 = e2;
#pragma unroll
    for (int q = 8; q > 0; q >>= 1) s2 += __shfl_xor_sync(F, s2, q, 16);

    if (lane < 16) {
        out0[node * 16 + lane] = o - m - logf(s1);
        out2[node * 16 + lane] = no - m2 - logf(s2);
    }
}

// ---------------------------------------------------------------------------
// Launch
// ---------------------------------------------------------------------------
extern "C" void kernel_launch(void* const* d_in, const int* in_sizes, int n_in,
                              void* d_out, int out_size)
{
    const float* x    = (const float*)d_in[0];
    const void*  ei   = d_in[1];
    // d_in[2] = attn_topk (always 8)
    const float* Wl1  = (const float*)d_in[3];
    const float* Wr1  = (const float*)d_in[4];
    const float* att1 = (const float*)d_in[5];
    const float* b1   = (const float*)d_in[6];
    const float* Wl2  = (const float*)d_in[7];
    const float* Wr2  = (const float*)d_in[8];
    const float* att2 = (const float*)d_in[9];
    const float* b2   = (const float*)d_in[10];
    const float* l1w  = (const float*)d_in[11];
    const float* l1b  = (const float*)d_in[12];
    const float* l2w  = (const float*)d_in[13];
    const float* l2b  = (const float*)d_in[14];

    int N = in_sizes[0] / 128;
    int E = in_sizes[1] / 2;
    if (N > MAXN) N = MAXN;
    if (E > MAXE) E = MAXE;

    float* out = (float*)d_out;
    float* out_s0 = out;
    float* out_s1 = out + (size_t)N * 16;
    float* out_s2 = out + (size_t)2 * N * 16;

    // Zero counters via async memset (graph-capturable, no alloc)
    void* p_counts = nullptr; void* p_cursor = nullptr;
    cudaGetSymbolAddress(&p_counts, d_counts);
    cudaGetSymbolAddress(&p_cursor, d_cursor);
    cudaMemsetAsync(p_counts, 0, (size_t)N * sizeof(int));
    cudaMemsetAsync(p_cursor, 0, (size_t)N * sizeof(int));

    detect_kernel<<<1, 32>>>(ei);
    convert_kernel<<<(E + 255) / 256, 256>>>(ei, E);
    scan_kernel<<<1, 1024>>>(N);
    scatter_kernel<<<(E + 255) / 256, 256>>>(E);

    // Layer 1
    gemm1_kernel<<<(N + 31) / 32, 256>>>(x, Wl1, Wr1, N);
    score1_kernel<<<(E + 7) / 8, 256>>>(att1, E);
    agg1_kernel<<<(N * 4 + 7) / 8, 256>>>(b1, N, E);

    // Layer 2 projections + MLP branch
    gemm2_kernel<<<(N + 47) / 48, 256>>>(Wl2, Wr2, N);
    mlp_kernel<<<(N + 31) / 32, 256>>>(l1w, l1b, l2w, l2b, out_s1, N);

    // Layer 2 attention
    score2_kernel<<<(E + 63) / 64, 256>>>(att2, E);
    agg2_kernel<<<(N + 7) / 8, 256>>>(b2, out_s0, out_s2, N);
}